// round 8
// baseline (speedup 1.0000x reference)
#include <cuda_runtime.h>
#include <cuda_bf16.h>
#include <cuda_fp16.h>
#include <cstdint>

// CuGraphSAGEConv, fused pipeline:
//   K0 convert: x(f32) -> g_xh(fp16); W(f32) -> g_wcvt bf16 hi/lo
//   K1 fused:   per block of 128 nodes:
//                 phase1: agg = mean fp16 neighbors -> bf16 hi/lo SMEM A-tiles
//                         (+ root x f32 split in-register into A-tiles)
//                 phase2: ldmatrix + mma.sync bf16 3-pass split GEMM, +bias.

#define D_IN  64
#define DK    128
#define D_OUT 64

#define NPAD  100352
__device__ __half        g_xh[(size_t)NPAD * D_IN];
__device__ unsigned char g_wcvt[64 * 512];   // [w_hi 256B | w_lo 256B] per out row

// ======================= helpers =======================
__device__ __forceinline__ uint32_t smem_u32(const void* p) {
    uint32_t a;
    asm("{ .reg .u64 t; cvta.to.shared.u64 t, %1; cvt.u32.u64 %0, t; }"
        : "=r"(a) : "l"(p));
    return a;
}
__device__ __forceinline__ uint2 split2(float v0, float v1) {
    __nv_bfloat16 h0 = __float2bfloat16_rn(v0);
    __nv_bfloat16 h1 = __float2bfloat16_rn(v1);
    float r0 = v0 - __bfloat162float(h0);
    float r1 = v1 - __bfloat162float(h1);
    __nv_bfloat162 hh = __halves2bfloat162(h0, h1);
    __nv_bfloat162 ll = __halves2bfloat162(__float2bfloat16_rn(r0),
                                           __float2bfloat16_rn(r1));
    uint2 r;
    r.x = *reinterpret_cast<uint32_t*>(&hh);
    r.y = *reinterpret_cast<uint32_t*>(&ll);
    return r;
}
__device__ __forceinline__ void ldm_x4(uint4& r, uint32_t addr) {
    asm volatile("ldmatrix.sync.aligned.m8n8.x4.shared.b16 {%0,%1,%2,%3}, [%4];"
                 : "=r"(r.x), "=r"(r.y), "=r"(r.z), "=r"(r.w) : "r"(addr));
}
__device__ __forceinline__ void mma16816(float* c, const uint4& a,
                                         uint32_t b0, uint32_t b1) {
    asm volatile(
        "mma.sync.aligned.m16n8k16.row.col.f32.bf16.bf16.f32 "
        "{%0,%1,%2,%3}, {%4,%5,%6,%7}, {%8,%9}, {%0,%1,%2,%3};"
        : "+f"(c[0]), "+f"(c[1]), "+f"(c[2]), "+f"(c[3])
        : "r"(a.x), "r"(a.y), "r"(a.z), "r"(a.w), "r"(b0), "r"(b1));
}
__device__ __forceinline__ void cp16(uint32_t dst, const void* src) {
    asm volatile("cp.async.cg.shared.global [%0], [%1], 16;"
                 :: "r"(dst), "l"(src));
}
__device__ __forceinline__ __half2 u2h(uint32_t u) {
    return *reinterpret_cast<__half2*>(&u);
}

// ======================= K0: convert x and W =======================
#define XBLOCKS 6272       // NPAD*16/256

__global__ __launch_bounds__(256)
void convert_kernel(const float4* __restrict__ x4,
                    const float4* __restrict__ W4, int N)
{
    if (blockIdx.x >= XBLOCKS) {
        const int idx = (blockIdx.x - XBLOCKS) * 256 + threadIdx.x;  // 0..2047
        const int o = idx >> 5;
        const int q = idx & 31;
        float4 v = __ldg(W4 + idx);
        uint2 p0 = split2(v.x, v.y);
        uint2 p1 = split2(v.z, v.w);
        unsigned char* wr = g_wcvt + (size_t)o * 512;
        *reinterpret_cast<uint2*>(wr + q * 8)       = make_uint2(p0.x, p1.x);
        *reinterpret_cast<uint2*>(wr + 256 + q * 8) = make_uint2(p0.y, p1.y);
        return;
    }
    const int idx  = blockIdx.x * 256 + threadIdx.x;
    const int node = idx >> 4;
    const int gl   = idx & 15;

    float4 v = make_float4(0.f, 0.f, 0.f, 0.f);
    if (node < N) v = __ldg(x4 + (size_t)node * 16 + gl);

    __half2 h01 = __floats2half2_rn(v.x, v.y);
    __half2 h23 = __floats2half2_rn(v.z, v.w);
    uint2 hp;
    hp.x = *reinterpret_cast<uint32_t*>(&h01);
    hp.y = *reinterpret_cast<uint32_t*>(&h23);
    reinterpret_cast<uint2*>(g_xh)[(size_t)node * 16 + gl] = hp;
}

// ======================= K1: fused gather + GEMM =======================
#define GB   128
#define ROWB 272
#define SM_AHI 0
#define SM_ALO 34816
#define SM_WHI 69632
#define SM_WLO 87040
#define SM_TOT 104448

extern __shared__ char g_sm[];

__global__ __launch_bounds__(256, 2)
void sage_fused_kernel(const float*  __restrict__ x,
                       const int*    __restrict__ row,
                       const int*    __restrict__ colptr,
                       const float*  __restrict__ b,
                       float*        __restrict__ out,
                       int N)
{
    const uint32_t sb = smem_u32(g_sm);
    const int tid  = threadIdx.x;
    const int wid  = tid >> 5;
    const int lane = tid & 31;
    const int base = blockIdx.x * GB;

    // ---- prefetch W tiles via cp.async (absorbed under gather phase) ----
    #pragma unroll
    for (int j = 0; j < 8; j++) {
        const int c = tid + 256 * j;          // 0..2047
        const int o = c >> 5;
        const int q = c & 31;                 // 0..15 hi, 16..31 lo
        const unsigned char* src = g_wcvt + (size_t)o * 512 + q * 16;
        const uint32_t dst = sb + (q < 16 ? SM_WHI : SM_WLO)
                             + o * ROWB + (q & 15) * 16;
        cp16(dst, src);
    }
    asm volatile("cp.async.commit_group;" ::: "memory");

    // ---- phase 1: gather, 8-lane group per node, 4 nodes per group ----
    {
        const int gi = tid >> 3;          // group 0..31
        const int gl = tid & 7;
        const uint4* xh4 = reinterpret_cast<const uint4*>(g_xh);
        const float4* xf4 = reinterpret_cast<const float4*>(x);

        #pragma unroll 1
        for (int i = 0; i < 4; i++) {
            const int nl = gi * 4 + i;               // local node 0..127
            const int mg = min(base + nl, N - 1);

            const int e0 = __ldg(colptr + mg);
            const int e1 = __ldg(colptr + mg + 1);

            float acc[8];
            #pragma unroll
            for (int k = 0; k < 8; k++) acc[k] = 0.f;

            int e = e0;
            if (e + 4 <= e1) {
                int sa0 = __ldg(row + e), sa1 = __ldg(row + e + 1);
                int sa2 = __ldg(row + e + 2), sa3 = __ldg(row + e + 3);
                e += 4;
                while (true) {
                    bool more = (e + 4 <= e1);
                    int sb0 = 0, sb1 = 0, sb2 = 0, sb3 = 0;
                    if (more) {
                        sb0 = __ldg(row + e);     sb1 = __ldg(row + e + 1);
                        sb2 = __ldg(row + e + 2); sb3 = __ldg(row + e + 3);
                    }
                    uint4 v0 = __ldg(xh4 + (size_t)sa0 * 8 + gl);
                    uint4 v1 = __ldg(xh4 + (size_t)sa1 * 8 + gl);
                    uint4 v2 = __ldg(xh4 + (size_t)sa2 * 8 + gl);
                    uint4 v3 = __ldg(xh4 + (size_t)sa3 * 8 + gl);
                    __half2 s0 = __hadd2(__hadd2(u2h(v0.x), u2h(v1.x)),
                                         __hadd2(u2h(v2.x), u2h(v3.x)));
                    __half2 s1 = __hadd2(__hadd2(u2h(v0.y), u2h(v1.y)),
                                         __hadd2(u2h(v2.y), u2h(v3.y)));
                    __half2 s2 = __hadd2(__hadd2(u2h(v0.z), u2h(v1.z)),
                                         __hadd2(u2h(v2.z), u2h(v3.z)));
                    __half2 s3 = __hadd2(__hadd2(u2h(v0.w), u2h(v1.w)),
                                         __hadd2(u2h(v2.w), u2h(v3.w)));
                    float2 f;
                    f = __half22float2(s0); acc[0] += f.x; acc[1] += f.y;
                    f = __half22float2(s1); acc[2] += f.x; acc[3] += f.y;
                    f = __half22float2(s2); acc[4] += f.x; acc[5] += f.y;
                    f = __half22float2(s3); acc[6] += f.x; acc[7] += f.y;
                    if (!more) break;
                    sa0 = sb0; sa1 = sb1; sa2 = sb2; sa3 = sb3;
                    e += 4;
                }
            }
            for (; e < e1; e++) {
                int s = __ldg(row + e);
                uint4 v = __ldg(xh4 + (size_t)s * 8 + gl);
                float2 f;
                f = __half22float2(u2h(v.x)); acc[0] += f.x; acc[1] += f.y;
                f = __half22float2(u2h(v.y)); acc[2] += f.x; acc[3] += f.y;
                f = __half22float2(u2h(v.z)); acc[4] += f.x; acc[5] += f.y;
                f = __half22float2(u2h(v.w)); acc[6] += f.x; acc[7] += f.y;
            }

            const int deg = e1 - e0;
            const float inv = 1.f / (float)(deg > 0 ? deg : 1);
            #pragma unroll
            for (int k = 0; k < 8; k++) acc[k] *= inv;

            // root features (f32)
            float4 r0 = __ldg(xf4 + (size_t)mg * 16 + 2 * gl);
            float4 r1 = __ldg(xf4 + (size_t)mg * 16 + 2 * gl + 1);

            // split + store to SMEM A tiles: row nl, agg at bytes [0,128),
            // x at [128,256)
            uint2 a0 = split2(acc[0], acc[1]);
            uint2 a1 = split2(acc[2], acc[3]);
            uint2 a2 = split2(acc[4], acc[5]);
            uint2 a3 = split2(acc[6], acc[7]);
            uint2 x0 = split2(r0.x, r0.y);
            uint2 x1 = split2(r0.z, r0.w);
            uint2 x2 = split2(r1.x, r1.y);
            uint2 x3 = split2(r1.z, r1.w);

            char* hi = g_sm + SM_AHI + nl * ROWB;
            char* lo = g_sm + SM_ALO + nl * ROWB;
            *reinterpret_cast<uint4*>(hi + gl * 16) =
                make_uint4(a0.x, a1.x, a2.x, a3.x);
            *reinterpret_cast<uint4*>(lo + gl * 16) =
                make_uint4(a0.y, a1.y, a2.y, a3.y);
            *reinterpret_cast<uint4*>(hi + 128 + gl * 16) =
                make_uint4(x0.x, x1.x, x2.x, x3.x);
            *reinterpret_cast<uint4*>(lo + 128 + gl * 16) =
                make_uint4(x0.y, x1.y, x2.y, x3.y);
        }
    }

    asm volatile("cp.async.wait_group 0;" ::: "memory");
    __syncthreads();

    // ---- phase 2: HMMA (identical to proven K2) ----
    const int wm = wid >> 1;
    const int wn = wid & 1;

    const uint32_t a_base = sb + SM_AHI
        + (uint32_t)(wm * 32 + (lane & 15)) * ROWB + (uint32_t)(lane >> 4) * 16;
    const int brow = wn * 32 + ((lane >> 4) << 3) + (lane & 7);
    const uint32_t b_base = sb + SM_WHI
        + (uint32_t)brow * ROWB + (uint32_t)((lane >> 3) & 1) * 16;

    float acc[2][4][4];
    #pragma unroll
    for (int i = 0; i < 2; i++)
        #pragma unroll
        for (int j = 0; j < 4; j++)
            #pragma unroll
            for (int q = 0; q < 4; q++) acc[i][j][q] = 0.f;

    #pragma unroll
    for (int ks = 0; ks < 8; ks++) {
        const uint32_t ao = a_base + ks * 32;
        const uint32_t bo = b_base + ks * 32;
        uint4 ah0, ah1, al0, al1, bh0, bh1, bl0, bl1;
        ldm_x4(ah0, ao);
        ldm_x4(ah1, ao + 16 * ROWB);
        ldm_x4(al0, ao + (SM_ALO - SM_AHI));
        ldm_x4(al1, ao + (SM_ALO - SM_AHI) + 16 * ROWB);
        ldm_x4(bh0, bo);
        ldm_x4(bh1, bo + 16 * ROWB);
        ldm_x4(bl0, bo + (SM_WLO - SM_WHI));
        ldm_x4(bl1, bo + (SM_WLO - SM_WHI) + 16 * ROWB);

        mma16816(acc[0][0], ah0, bh0.x, bh0.y);
        mma16816(acc[0][1], ah0, bh0.z, bh0.w);
        mma16816(acc[0][2], ah0, bh1.x, bh1.y);
        mma16816(acc[0][3], ah0, bh1.z, bh1.w);
        mma16816(acc[1][0], ah1, bh0.x, bh0.y);
        mma16816(acc[1][1], ah1, bh0.z, bh0.w);
        mma16816(acc[1][2], ah1, bh1.x, bh1.y);
        mma16816(acc[1][3], ah1, bh1.z, bh1.w);

        mma16816(acc[0][0], ah0, bl0.x, bl0.y);
        mma16816(acc[0][1], ah0, bl0.z, bl0.w);
        mma16816(acc[0][2], ah0, bl1.x, bl1.y);
        mma16816(acc[0][3], ah0, bl1.z, bl1.w);
        mma16816(acc[1][0], ah1, bl0.x, bl0.y);
        mma16816(acc[1][1], ah1, bl0.z, bl0.w);
        mma16816(acc[1][2], ah1, bl1.x, bl1.y);
        mma16816(acc[1][3], ah1, bl1.z, bl1.w);

        mma16816(acc[0][0], al0, bh0.x, bh0.y);
        mma16816(acc[0][1], al0, bh0.z, bh0.w);
        mma16816(acc[0][2], al0, bh1.x, bh1.y);
        mma16816(acc[0][3], al0, bh1.z, bh1.w);
        mma16816(acc[1][0], al1, bh0.x, bh0.y);
        mma16816(acc[1][1], al1, bh0.z, bh0.w);
        mma16816(acc[1][2], al1, bh1.x, bh1.y);
        mma16816(acc[1][3], al1, bh1.z, bh1.w);
    }

    // ---- epilogue ----
    const int g   = lane >> 2;
    const int tig = lane & 3;
    float2 bb[4];
    #pragma unroll
    for (int ns = 0; ns < 4; ns++) {
        int col = wn * 32 + ns * 8 + 2 * tig;
        bb[ns] = make_float2(__ldg(b + col), __ldg(b + col + 1));
    }
    #pragma unroll
    for (int ms = 0; ms < 2; ms++) {
        const int node0 = base + wm * 32 + ms * 16 + g;
        const int node1 = node0 + 8;
        #pragma unroll
        for (int ns = 0; ns < 4; ns++) {
            const int col = wn * 32 + ns * 8 + 2 * tig;
            if (node0 < N) {
                *reinterpret_cast<float2*>(out + (size_t)node0 * D_OUT + col) =
                    make_float2(acc[ms][ns][0] + bb[ns].x, acc[ms][ns][1] + bb[ns].y);
            }
            if (node1 < N) {
                *reinterpret_cast<float2*>(out + (size_t)node1 * D_OUT + col) =
                    make_float2(acc[ms][ns][2] + bb[ns].x, acc[ms][ns][3] + bb[ns].y);
            }
        }
    }
}

// ======================= launch =======================
extern "C" void kernel_launch(void* const* d_in, const int* in_sizes, int n_in,
                              void* d_out, int out_size)
{
    const float* x      = (const float*)d_in[0];
    const int*   row    = (const int*)  d_in[1];
    const int*   colptr = (const int*)  d_in[2];
    const float* W      = (const float*)d_in[3];
    const float* b      = (const float*)d_in[4];
    float*       out    = (float*)d_out;

    const int N = in_sizes[2] - 1;   // 100000

    cudaFuncSetAttribute(sage_fused_kernel,
                         cudaFuncAttributeMaxDynamicSharedMemorySize, SM_TOT);

    convert_kernel<<<XBLOCKS + 8, 256>>>(
        reinterpret_cast<const float4*>(x),
        reinterpret_cast<const float4*>(W), N);

    int grid = (N + GB - 1) / GB;
    sage_fused_kernel<<<grid, 256, SM_TOT>>>(x, row, colptr, b, out, N);
}

// round 9
// speedup vs baseline: 1.2116x; 1.2116x over previous
#include <cuda_runtime.h>
#include <cuda_bf16.h>
#include <cuda_fp16.h>
#include <cstdint>

// CuGraphSAGEConv pipeline (3 kernels, pipelined GEMM):
//   K0 convert: x -> g_xh(fp16) + feat x hi/lo(bf16); W -> g_wcvt hi/lo
//   K1 gather:  agg = mean fp16 neighbors (8-edge dual-tree HADD2) -> feat
//   K2 gemm:    multi-tile double-buffered cp.async + mma.sync 3-pass bf16

#define D_IN  64
#define DK    128
#define D_OUT 64

#define NPAD  100352
// feat row (512B): [agg_hi 128B | x_hi 128B | agg_lo 128B | x_lo 128B]
__device__ unsigned char g_feat[(size_t)NPAD * 512];
__device__ __half        g_xh[(size_t)NPAD * D_IN];
__device__ unsigned char g_wcvt[64 * 512];

// ======================= helpers =======================
__device__ __forceinline__ uint32_t smem_u32(const void* p) {
    uint32_t a;
    asm("{ .reg .u64 t; cvta.to.shared.u64 t, %1; cvt.u32.u64 %0, t; }"
        : "=r"(a) : "l"(p));
    return a;
}
__device__ __forceinline__ uint2 split2(float v0, float v1) {
    __nv_bfloat16 h0 = __float2bfloat16_rn(v0);
    __nv_bfloat16 h1 = __float2bfloat16_rn(v1);
    float r0 = v0 - __bfloat162float(h0);
    float r1 = v1 - __bfloat162float(h1);
    __nv_bfloat162 hh = __halves2bfloat162(h0, h1);
    __nv_bfloat162 ll = __halves2bfloat162(__float2bfloat16_rn(r0),
                                           __float2bfloat16_rn(r1));
    uint2 r;
    r.x = *reinterpret_cast<uint32_t*>(&hh);
    r.y = *reinterpret_cast<uint32_t*>(&ll);
    return r;
}
__device__ __forceinline__ void ldm_x4(uint4& r, uint32_t addr) {
    asm volatile("ldmatrix.sync.aligned.m8n8.x4.shared.b16 {%0,%1,%2,%3}, [%4];"
                 : "=r"(r.x), "=r"(r.y), "=r"(r.z), "=r"(r.w) : "r"(addr));
}
__device__ __forceinline__ void mma16816(float* c, const uint4& a,
                                         uint32_t b0, uint32_t b1) {
    asm volatile(
        "mma.sync.aligned.m16n8k16.row.col.f32.bf16.bf16.f32 "
        "{%0,%1,%2,%3}, {%4,%5,%6,%7}, {%8,%9}, {%0,%1,%2,%3};"
        : "+f"(c[0]), "+f"(c[1]), "+f"(c[2]), "+f"(c[3])
        : "r"(a.x), "r"(a.y), "r"(a.z), "r"(a.w), "r"(b0), "r"(b1));
}
__device__ __forceinline__ void cp16(uint32_t dst, const void* src) {
    asm volatile("cp.async.cg.shared.global [%0], [%1], 16;"
                 :: "r"(dst), "l"(src));
}
__device__ __forceinline__ __half2 u2h(uint32_t u) {
    return *reinterpret_cast<__half2*>(&u);
}
// 4-value HADD2 tree -> f32 accumulate
__device__ __forceinline__ void tree4(float* acc, const uint4& v0, const uint4& v1,
                                      const uint4& v2, const uint4& v3) {
    __half2 s0 = __hadd2(__hadd2(u2h(v0.x), u2h(v1.x)), __hadd2(u2h(v2.x), u2h(v3.x)));
    __half2 s1 = __hadd2(__hadd2(u2h(v0.y), u2h(v1.y)), __hadd2(u2h(v2.y), u2h(v3.y)));
    __half2 s2 = __hadd2(__hadd2(u2h(v0.z), u2h(v1.z)), __hadd2(u2h(v2.z), u2h(v3.z)));
    __half2 s3 = __hadd2(__hadd2(u2h(v0.w), u2h(v1.w)), __hadd2(u2h(v2.w), u2h(v3.w)));
    float2 f;
    f = __half22float2(s0); acc[0] += f.x; acc[1] += f.y;
    f = __half22float2(s1); acc[2] += f.x; acc[3] += f.y;
    f = __half22float2(s2); acc[4] += f.x; acc[5] += f.y;
    f = __half22float2(s3); acc[6] += f.x; acc[7] += f.y;
}

// ======================= K0: convert x and W =======================
#define XBLOCKS 6272       // NPAD*16/256

__global__ __launch_bounds__(256)
void convert_kernel(const float4* __restrict__ x4,
                    const float4* __restrict__ W4, int N)
{
    if (blockIdx.x >= XBLOCKS) {
        const int idx = (blockIdx.x - XBLOCKS) * 256 + threadIdx.x;  // 0..2047
        const int o = idx >> 5;
        const int q = idx & 31;
        float4 v = __ldg(W4 + idx);
        uint2 p0 = split2(v.x, v.y);
        uint2 p1 = split2(v.z, v.w);
        unsigned char* wr = g_wcvt + (size_t)o * 512;
        *reinterpret_cast<uint2*>(wr + q * 8)       = make_uint2(p0.x, p1.x);
        *reinterpret_cast<uint2*>(wr + 256 + q * 8) = make_uint2(p0.y, p1.y);
        return;
    }
    const int idx  = blockIdx.x * 256 + threadIdx.x;
    const int node = idx >> 4;
    const int gl   = idx & 15;

    float4 v = make_float4(0.f, 0.f, 0.f, 0.f);
    if (node < N) v = __ldg(x4 + (size_t)node * 16 + gl);

    __half2 h01 = __floats2half2_rn(v.x, v.y);
    __half2 h23 = __floats2half2_rn(v.z, v.w);
    uint2 hp;
    hp.x = *reinterpret_cast<uint32_t*>(&h01);
    hp.y = *reinterpret_cast<uint32_t*>(&h23);
    reinterpret_cast<uint2*>(g_xh)[(size_t)node * 16 + gl] = hp;

    uint2 p0 = split2(v.x, v.y);
    uint2 p1 = split2(v.z, v.w);
    unsigned char* fr = g_feat + (size_t)node * 512;
    *reinterpret_cast<uint2*>(fr + 128 + gl * 8) = make_uint2(p0.x, p1.x);
    *reinterpret_cast<uint2*>(fr + 384 + gl * 8) = make_uint2(p0.y, p1.y);
}

// ======================= K1: gather =======================
__global__ __launch_bounds__(256)
void gather_kernel(const int* __restrict__ row,
                   const int* __restrict__ colptr,
                   int N)
{
    const int g  = (blockIdx.x * 256 + threadIdx.x) >> 3;
    const int gl = threadIdx.x & 7;
    if (g >= N) return;

    const uint4* xh4 = reinterpret_cast<const uint4*>(g_xh);

    const int e0 = __ldg(colptr + g);
    const int e1 = __ldg(colptr + g + 1);

    float acc[8];
    #pragma unroll
    for (int i = 0; i < 8; i++) acc[i] = 0.f;

    int e = e0;
    // 8-edge main loop: two independent 4-trees, 8 value loads in flight
    if (e + 8 <= e1) {
        int s[8];
        #pragma unroll
        for (int j = 0; j < 8; j++) s[j] = __ldg(row + e + j);
        e += 8;
        while (true) {
            bool more = (e + 8 <= e1);
            int t[8];
            if (more) {
                #pragma unroll
                for (int j = 0; j < 8; j++) t[j] = __ldg(row + e + j);
            }
            uint4 v0 = __ldg(xh4 + (size_t)s[0] * 8 + gl);
            uint4 v1 = __ldg(xh4 + (size_t)s[1] * 8 + gl);
            uint4 v2 = __ldg(xh4 + (size_t)s[2] * 8 + gl);
            uint4 v3 = __ldg(xh4 + (size_t)s[3] * 8 + gl);
            uint4 v4 = __ldg(xh4 + (size_t)s[4] * 8 + gl);
            uint4 v5 = __ldg(xh4 + (size_t)s[5] * 8 + gl);
            uint4 v6 = __ldg(xh4 + (size_t)s[6] * 8 + gl);
            uint4 v7 = __ldg(xh4 + (size_t)s[7] * 8 + gl);
            tree4(acc, v0, v1, v2, v3);
            tree4(acc, v4, v5, v6, v7);
            if (!more) break;
            #pragma unroll
            for (int j = 0; j < 8; j++) s[j] = t[j];
            e += 8;
        }
    }
    if (e + 4 <= e1) {
        int s0 = __ldg(row + e), s1 = __ldg(row + e + 1);
        int s2 = __ldg(row + e + 2), s3 = __ldg(row + e + 3);
        uint4 v0 = __ldg(xh4 + (size_t)s0 * 8 + gl);
        uint4 v1 = __ldg(xh4 + (size_t)s1 * 8 + gl);
        uint4 v2 = __ldg(xh4 + (size_t)s2 * 8 + gl);
        uint4 v3 = __ldg(xh4 + (size_t)s3 * 8 + gl);
        tree4(acc, v0, v1, v2, v3);
        e += 4;
    }
    for (; e < e1; e++) {
        int s = __ldg(row + e);
        uint4 v = __ldg(xh4 + (size_t)s * 8 + gl);
        float2 f;
        f = __half22float2(u2h(v.x)); acc[0] += f.x; acc[1] += f.y;
        f = __half22float2(u2h(v.y)); acc[2] += f.x; acc[3] += f.y;
        f = __half22float2(u2h(v.z)); acc[4] += f.x; acc[5] += f.y;
        f = __half22float2(u2h(v.w)); acc[6] += f.x; acc[7] += f.y;
    }

    const int deg = e1 - e0;
    const float inv = 1.f / (float)(deg > 0 ? deg : 1);
    #pragma unroll
    for (int i = 0; i < 8; i++) acc[i] *= inv;

    uint2 p0 = split2(acc[0], acc[1]);
    uint2 p1 = split2(acc[2], acc[3]);
    uint2 p2 = split2(acc[4], acc[5]);
    uint2 p3 = split2(acc[6], acc[7]);
    unsigned char* fr = g_feat + (size_t)g * 512;
    *reinterpret_cast<uint4*>(fr + gl * 16)       = make_uint4(p0.x, p1.x, p2.x, p3.x);
    *reinterpret_cast<uint4*>(fr + 256 + gl * 16) = make_uint4(p0.y, p1.y, p2.y, p3.y);
}

// ======================= K2: pipelined HMMA GEMM =======================
#define TB     64        // nodes per tile
#define ROWB   272
#define SM_WHI 0
#define SM_WLO 17408
#define SM_A0  34816     // buffer 0: [AHI 17408 | ALO 17408]
#define SM_A1  69632     // buffer 1
#define ABUF   34816
#define SM_TOT 104448
#define GRID2  296       // 2 CTAs/SM * 148

extern __shared__ char g_sm[];

__device__ __forceinline__ void stage_tile(uint32_t sb, int buf, int tbase, int tid)
{
    const uint32_t abase = sb + (buf ? SM_A1 : SM_A0);
    #pragma unroll
    for (int j = 0; j < 8; j++) {
        const int c   = tid + 256 * j;      // 0..2047
        const int r   = c >> 5;             // row 0..63
        const int q   = c & 31;             // 0..15 hi, 16..31 lo
        const unsigned char* src = g_feat + (size_t)(tbase + r) * 512 + q * 16;
        const uint32_t dst = abase + (q < 16 ? 0 : 17408)
                             + r * ROWB + (q & 15) * 16;
        cp16(dst, src);
    }
    asm volatile("cp.async.commit_group;" ::: "memory");
}

__global__ __launch_bounds__(256, 2)
void gemm_mma_kernel(const float* __restrict__ b,
                     float*       __restrict__ out,
                     int N, int ntiles)
{
    const uint32_t sb = smem_u32(g_sm);
    const int tid  = threadIdx.x;
    const int wid  = tid >> 5;
    const int lane = tid & 31;

    // ---- stage W (once per block) ----
    #pragma unroll
    for (int j = 0; j < 8; j++) {
        const int c = tid + 256 * j;
        const int o = c >> 5;
        const int q = c & 31;
        const unsigned char* src = g_wcvt + (size_t)o * 512 + q * 16;
        const uint32_t dst = sb + (q < 16 ? SM_WHI : SM_WLO)
                             + o * ROWB + (q & 15) * 16;
        cp16(dst, src);
    }
    asm volatile("cp.async.commit_group;" ::: "memory");

    int t0 = blockIdx.x;
    if (t0 < ntiles) stage_tile(sb, 0, t0 * TB, tid);

    // warp grid: 4 m-warps (16 rows each) x 2 n-warps (32 cols each)
    const int wm = wid >> 1;
    const int wn = wid & 1;

    const uint32_t a_off = (uint32_t)(wm * 16 + (lane & 15)) * ROWB
                           + (uint32_t)(lane >> 4) * 16;
    const int brow = wn * 32 + ((lane >> 4) << 3) + (lane & 7);
    const uint32_t b_base = sb + SM_WHI
        + (uint32_t)brow * ROWB + (uint32_t)((lane >> 3) & 1) * 16;

    const int g   = lane >> 2;
    const int tig = lane & 3;
    float2 bb[4];
    #pragma unroll
    for (int ns = 0; ns < 4; ns++) {
        int col = wn * 32 + ns * 8 + 2 * tig;
        bb[ns] = make_float2(__ldg(b + col), __ldg(b + col + 1));
    }

    int i = 0;
    for (int t = t0; t < ntiles; t += GRID2, i++) {
        const int nxt = t + GRID2;
        if (nxt < ntiles) {
            stage_tile(sb, (i + 1) & 1, nxt * TB, tid);
            asm volatile("cp.async.wait_group 1;" ::: "memory");
        } else {
            asm volatile("cp.async.wait_group 0;" ::: "memory");
        }
        __syncthreads();

        const uint32_t a_base = sb + ((i & 1) ? SM_A1 : SM_A0) + a_off;

        float acc[4][4];
        #pragma unroll
        for (int ns = 0; ns < 4; ns++)
            #pragma unroll
            for (int q = 0; q < 4; q++) acc[ns][q] = 0.f;

        #pragma unroll
        for (int ks = 0; ks < 8; ks++) {
            const uint32_t ao = a_base + ks * 32;
            const uint32_t bo = b_base + ks * 32;
            uint4 ah, al, bh0, bh1, bl0, bl1;
            ldm_x4(ah, ao);
            ldm_x4(al, ao + 17408);
            ldm_x4(bh0, bo);
            ldm_x4(bh1, bo + 16 * ROWB);
            ldm_x4(bl0, bo + (SM_WLO - SM_WHI));
            ldm_x4(bl1, bo + (SM_WLO - SM_WHI) + 16 * ROWB);

            mma16816(acc[0], ah, bh0.x, bh0.y);
            mma16816(acc[1], ah, bh0.z, bh0.w);
            mma16816(acc[2], ah, bh1.x, bh1.y);
            mma16816(acc[3], ah, bh1.z, bh1.w);

            mma16816(acc[0], ah, bl0.x, bl0.y);
            mma16816(acc[1], ah, bl0.z, bl0.w);
            mma16816(acc[2], ah, bl1.x, bl1.y);
            mma16816(acc[3], ah, bl1.z, bl1.w);

            mma16816(acc[0], al, bh0.x, bh0.y);
            mma16816(acc[1], al, bh0.z, bh0.w);
            mma16816(acc[2], al, bh1.x, bh1.y);
            mma16816(acc[3], al, bh1.z, bh1.w);
        }

        // epilogue
        const int node0 = t * TB + wm * 16 + g;
        const int node1 = node0 + 8;
        #pragma unroll
        for (int ns = 0; ns < 4; ns++) {
            const int col = wn * 32 + ns * 8 + 2 * tig;
            if (node0 < N)
                *reinterpret_cast<float2*>(out + (size_t)node0 * D_OUT + col) =
                    make_float2(acc[ns][0] + bb[ns].x, acc[ns][1] + bb[ns].y);
            if (node1 < N)
                *reinterpret_cast<float2*>(out + (size_t)node1 * D_OUT + col) =
                    make_float2(acc[ns][2] + bb[ns].x, acc[ns][3] + bb[ns].y);
        }
        __syncthreads();   // protect buffer (i&1) before refill at i+2
    }
}

// ======================= launch =======================
extern "C" void kernel_launch(void* const* d_in, const int* in_sizes, int n_in,
                              void* d_out, int out_size)
{
    const float* x      = (const float*)d_in[0];
    const int*   row    = (const int*)  d_in[1];
    const int*   colptr = (const int*)  d_in[2];
    const float* W      = (const float*)d_in[3];
    const float* b      = (const float*)d_in[4];
    float*       out    = (float*)d_out;

    const int N = in_sizes[2] - 1;   // 100000
    const int ntiles = (N + TB - 1) / TB;

    cudaFuncSetAttribute(gemm_mma_kernel,
                         cudaFuncAttributeMaxDynamicSharedMemorySize, SM_TOT);

    convert_kernel<<<XBLOCKS + 8, 256>>>(
        reinterpret_cast<const float4*>(x),
        reinterpret_cast<const float4*>(W), N);

    gather_kernel<<<(N * 8 + 255) / 256, 256>>>(row, colptr, N);

    gemm_mma_kernel<<<GRID2, 256, SM_TOT>>>(b, out, N, ntiles);
}